// round 2
// baseline (speedup 1.0000x reference)
#include <cuda_runtime.h>
#include <cstdint>

#define TM 64
#define TN 64
#define DD 128
#define NTHREADS 256
#define MAXB 8192

// per-row scratch (no allocations allowed)
__device__ float g_rowloss[MAXB];
__device__ int   g_rowcorr[MAXB];

__device__ __forceinline__ void ffma2(unsigned long long &d,
                                      unsigned long long a,
                                      unsigned long long b) {
    // packed fp32x2 FMA (sm_103a): d.lo += a.lo*b.lo ; d.hi += a.hi*b.hi
    asm("fma.rn.f32x2 %0, %1, %2, %0;" : "+l"(d) : "l"(a), "l"(b));
}

__device__ __forceinline__ unsigned smem_u32(const void* p) {
    return (unsigned)__cvta_generic_to_shared(p);
}
__device__ __forceinline__ void cpa16(unsigned d, const void* s) {
    asm volatile("cp.async.cg.shared.global [%0], [%1], 16;" :: "r"(d), "l"(s));
}
__device__ __forceinline__ void cpa4(unsigned d, const void* s) {
    asm volatile("cp.async.ca.shared.global [%0], [%1], 4;" :: "r"(d), "l"(s));
}
__device__ __forceinline__ void cp_commit() {
    asm volatile("cp.async.commit_group;");
}
__device__ __forceinline__ void cp_wait0() {
    asm volatile("cp.async.wait_group 0;");
}

// Fused GEMM (sims = Q @ A^T) + online softmax-ratio + argmax epilogue.
// Grid: B/TM CTAs, 256 threads (16x16), each thread owns a 4x4 micro-tile.
// SMEM: Qs[64][128] (loaded once) + double-buffered As[2][64][128] + ids/ranks.
// Chunk-XOR swizzle: float4-chunk pc = kc ^ ((row>>2)&7)  -> conflict-free
// LDS.128 for the stride-4-row fragment reads.
extern "C" __global__ void __launch_bounds__(NTHREADS, 1)
mpl_main(const float* __restrict__ Q, const float* __restrict__ A,
         const int* __restrict__ qid, const float* __restrict__ rnk,
         int B)
{
    extern __shared__ char sm[];
    float* Qs  = (float*)sm;                       // TM*DD floats
    float* As  = Qs + TM * DD;                     // 2 * TN*DD floats
    int*   qss = (int*)(sm + (size_t)(TM * DD + 2 * TN * DD) * 4);
    float* rss = (float*)((char*)qss + 2 * TN * sizeof(int));

    const int tid = threadIdx.x;
    const int tx  = tid & 15;
    const int ty  = tid >> 4;
    const int rbase = blockIdx.x * TM;
    const int nt = B / TN;

    // ---- prologue: Q tile + A tile 0 + ids/ranks tile 0 (async) ----
    #pragma unroll
    for (int i = 0; i < 8; i++) {
        int lin = tid + i * NTHREADS;
        int row = lin >> 5, kc = lin & 31;
        int pc  = kc ^ ((row >> 2) & 7);
        cpa16(smem_u32(Qs + row * DD + pc * 4),
              Q + (size_t)(rbase + row) * DD + kc * 4);
    }
    #pragma unroll
    for (int i = 0; i < 8; i++) {
        int lin = tid + i * NTHREADS;
        int col = lin >> 5, kc = lin & 31;
        int pc  = kc ^ ((col >> 2) & 7);
        cpa16(smem_u32(As + col * DD + pc * 4),
              A + (size_t)col * DD + kc * 4);
    }
    if (tid < TN) {
        cpa4(smem_u32(qss + tid), qid + tid);
        cpa4(smem_u32(rss + tid), rnk + tid);
    }
    cp_commit();

    int myqid[4];
    #pragma unroll
    for (int r = 0; r < 4; r++) myqid[r] = qid[rbase + 4 * ty + r];

    float m[4], den[4], num[4];
    int   idx[4], corr[4];
    #pragma unroll
    for (int r = 0; r < 4; r++) {
        m[r] = -3.4e38f; den[r] = 0.f; num[r] = 0.f;
        idx[r] = 0x7fffffff; corr[r] = 0;
    }

    cp_wait0();
    __syncthreads();

    const int qx = ty & 7, ax = tx & 7;

    for (int t = 0; t < nt; t++) {
        const int b = t & 1;

        // issue next A tile into the other buffer (overlaps with compute)
        if (t + 1 < nt) {
            const float* src = A + (size_t)(t + 1) * TN * DD;
            float* dst = As + (b ^ 1) * TN * DD;
            #pragma unroll
            for (int i = 0; i < 8; i++) {
                int lin = tid + i * NTHREADS;
                int col = lin >> 5, kc = lin & 31;
                int pc  = kc ^ ((col >> 2) & 7);
                cpa16(smem_u32(dst + col * DD + pc * 4),
                      src + (size_t)col * DD + kc * 4);
            }
            if (tid < TN) {
                cpa4(smem_u32(qss + (b ^ 1) * TN + tid), qid + (t + 1) * TN + tid);
                cpa4(smem_u32(rss + (b ^ 1) * TN + tid), rnk + (t + 1) * TN + tid);
            }
            cp_commit();
        }

        // ---- mainloop: 4x4 micro-tile, K paired for f32x2 FFMA ----
        const float* Ab = As + b * TN * DD;
        unsigned long long acc[4][4];
        #pragma unroll
        for (int r = 0; r < 4; r++)
            #pragma unroll
            for (int i = 0; i < 4; i++) acc[r][i] = 0ull;

        #pragma unroll 8
        for (int kc = 0; kc < 32; kc++) {
            ulonglong2 qv[4], av[4];
            #pragma unroll
            for (int r = 0; r < 4; r++)
                qv[r] = *(const ulonglong2*)(Qs + (4 * ty + r) * DD + ((kc ^ qx) << 2));
            #pragma unroll
            for (int i = 0; i < 4; i++)
                av[i] = *(const ulonglong2*)(Ab + (4 * tx + i) * DD + ((kc ^ ax) << 2));
            #pragma unroll
            for (int r = 0; r < 4; r++)
                #pragma unroll
                for (int i = 0; i < 4; i++) {
                    ffma2(acc[r][i], qv[r].x, av[i].x);
                    ffma2(acc[r][i], qv[r].y, av[i].y);
                }
        }

        // ---- fused epilogue: exp / weighted sums / running argmax ----
        const int cbase = t * TN;
        #pragma unroll
        for (int i = 0; i < 4; i++) {
            const int c = 4 * tx + i;
            const int   qj = qss[b * TN + c];
            const float wj = 1.0f - 0.1f * rss[b * TN + c];
            const int j = cbase + c;
            #pragma unroll
            for (int r = 0; r < 4; r++) {
                unsigned long long a = acc[r][i];
                float s = __uint_as_float((unsigned)a)
                        + __uint_as_float((unsigned)(a >> 32));
                float e = __expf(s);
                den[r] += e;
                bool same = (qj == myqid[r]);
                num[r] = fmaf(same ? wj : 0.0f, e, num[r]);
                if (s > m[r]) { m[r] = s; idx[r] = j; corr[r] = same ? 1 : 0; }
            }
        }

        if (t + 1 < nt) cp_wait0();
        __syncthreads();
    }

    // ---- cross-thread reduce over the 16 tx lanes sharing each row ----
    #pragma unroll
    for (int r = 0; r < 4; r++) {
        #pragma unroll
        for (int off = 8; off > 0; off >>= 1) {
            float om = __shfl_xor_sync(0xffffffffu, m[r],   off, 16);
            float od = __shfl_xor_sync(0xffffffffu, den[r], off, 16);
            float on = __shfl_xor_sync(0xffffffffu, num[r], off, 16);
            int   oi = __shfl_xor_sync(0xffffffffu, idx[r], off, 16);
            int   oc = __shfl_xor_sync(0xffffffffu, corr[r], off, 16);
            den[r] += od; num[r] += on;
            if (om > m[r] || (om == m[r] && oi < idx[r])) {
                m[r] = om; idx[r] = oi; corr[r] = oc;
            }
        }
        if (tx == 0) {
            int row = rbase + 4 * ty + r;
            g_rowloss[row] = -logf(num[r] / den[r] + 1e-8f);
            g_rowcorr[row] = corr[r];
        }
    }
}

extern "C" __global__ void mpl_finalize(float* out, int B, int osz)
{
    __shared__ float sf[256];
    __shared__ int   si[256];
    float s = 0.f; int c = 0;
    for (int i = threadIdx.x; i < B; i += blockDim.x) {
        s += g_rowloss[i];
        c += g_rowcorr[i];
    }
    sf[threadIdx.x] = s; si[threadIdx.x] = c;
    __syncthreads();
    for (int o = 128; o > 0; o >>= 1) {
        if (threadIdx.x < o) {
            sf[threadIdx.x] += sf[threadIdx.x + o];
            si[threadIdx.x] += si[threadIdx.x + o];
        }
        __syncthreads();
    }
    if (threadIdx.x == 0) {
        out[0] = sf[0] / (float)B;
        if (osz > 1) out[1] = (float)si[0] / (float)B;
    }
}

extern "C" void kernel_launch(void* const* d_in, const int* in_sizes, int n_in,
                              void* d_out, int out_size)
{
    const float* Q   = (const float*)d_in[0];
    const float* A   = (const float*)d_in[1];
    const int*   qid = (const int*)d_in[2];
    const float* rnk = (const float*)d_in[3];
    const int B = in_sizes[2];

    size_t smem = (size_t)(TM * DD + 2 * TN * DD) * sizeof(float)
                + 2 * TN * (sizeof(int) + sizeof(float));
    cudaFuncSetAttribute(mpl_main, cudaFuncAttributeMaxDynamicSharedMemorySize,
                         (int)smem);

    mpl_main<<<B / TM, NTHREADS, smem>>>(Q, A, qid, rnk, B);
    mpl_finalize<<<1, 256>>>((float*)d_out, B, out_size);
}

// round 4
// speedup vs baseline: 3.1528x; 3.1528x over previous
#include <cuda_runtime.h>
#include <cuda_bf16.h>
#include <cstdint>

#define MAXB 8192
#define DD   128
#define ROWT 128
#define COLT 128
#define CHUNKS 2
#define NTH  256

// ---------------- global scratch (no allocations allowed) ----------------
__device__ __nv_bfloat16 g_qhi[MAXB * DD], g_qlo[MAXB * DD];
__device__ __nv_bfloat16 g_ahi[MAXB * DD], g_alo[MAXB * DD];
__device__ float g_pden[CHUNKS][MAXB], g_pnum[CHUNKS][MAXB], g_pm[CHUNKS][MAXB];
__device__ int   g_pidx[CHUNKS][MAXB], g_pcorr[CHUNKS][MAXB];
__device__ float g_blkloss[64];
__device__ int   g_blkcorr[64];

// ---------------- smem layout (dynamic) ----------------
// Qhi[32K] Qlo[32K]  A[2 bufs][hi 32K | lo 32K]  ids[2][512] rnk[2][512]
#define SM_QHI   0
#define SM_QLO   32768
#define SM_A(b)  (65536 + (b) * 65536)
#define SM_IDS(b) (196608 + (b) * 512)
#define SM_RNK(b) (197632 + (b) * 512)
#define SMEM_TOTAL 198656

static __device__ __forceinline__ unsigned su32(const void* p) {
    return (unsigned)__cvta_generic_to_shared(p);
}
static __device__ __forceinline__ void cpa16(unsigned d, const void* s) {
    asm volatile("cp.async.cg.shared.global [%0], [%1], 16;" :: "r"(d), "l"(s));
}
static __device__ __forceinline__ void cpcommit() {
    asm volatile("cp.async.commit_group;");
}
static __device__ __forceinline__ void cpwait0() {
    asm volatile("cp.async.wait_group 0;");
}

// SW128-atom tile offset for a 128-row x 128-bf16 (256B-wide logical) tile,
// stored as two 128B halves: half = cc>>3 (k 0..63 | 64..127)
static __device__ __forceinline__ int toff(int r, int cc) {   // cc = 16B chunk 0..15
    return ((cc >> 3) << 14) + r * 128 + (((cc & 7) ^ (r & 7)) << 4);
}

#define LDSM4(rg, ad) asm volatile( \
    "ldmatrix.sync.aligned.m8n8.x4.shared.b16 {%0,%1,%2,%3}, [%4];" \
    : "=r"((rg)[0]), "=r"((rg)[1]), "=r"((rg)[2]), "=r"((rg)[3]) : "r"(ad))
#define LDSM2(rg, ad) asm volatile( \
    "ldmatrix.sync.aligned.m8n8.x2.shared.b16 {%0,%1}, [%2];" \
    : "=r"((rg)[0]), "=r"((rg)[1]) : "r"(ad))
#define MMA(dd, aa, bb) asm volatile( \
    "mma.sync.aligned.m16n8k16.row.col.f32.bf16.bf16.f32 " \
    "{%0,%1,%2,%3}, {%4,%5,%6,%7}, {%8,%9}, {%0,%1,%2,%3};" \
    : "+f"((dd)[0]), "+f"((dd)[1]), "+f"((dd)[2]), "+f"((dd)[3]) \
    : "r"((aa)[0]), "r"((aa)[1]), "r"((aa)[2]), "r"((aa)[3]), \
      "r"((bb)[0]), "r"((bb)[1]))

static __device__ __forceinline__ void load_a(uint32_t smb, int b, int gcol0) {
    for (int i = threadIdx.x; i < 2048; i += NTH) {
        int r = i >> 4, cc = i & 15;
        int off = toff(r, cc);
        size_t g = (size_t)(gcol0 + r) * DD + cc * 8;
        cpa16(smb + SM_A(b) + off, g_ahi + g);
        cpa16(smb + SM_A(b) + 32768 + off, g_alo + g);
    }
}
static __device__ __forceinline__ void load_meta(uint32_t smb, int b, int gcol0,
                                                 const int* qid, const float* rnk) {
    int t = threadIdx.x;
    if (t < 32) {
        cpa16(smb + SM_IDS(b) + t * 16, qid + gcol0 + t * 4);
        cpa16(smb + SM_RNK(b) + t * 16, rnk + gcol0 + t * 4);
    }
}

// -------------------- prep: fp32 -> bf16 hi/lo split --------------------
extern "C" __global__ void mpl_prep(const float* __restrict__ Q,
                                    const float* __restrict__ A, int n) {
    int i = blockIdx.x * blockDim.x + threadIdx.x;
    if (i < n) {
        float q = Q[i];
        __nv_bfloat16 h = __float2bfloat16(q);
        g_qhi[i] = h;
        g_qlo[i] = __float2bfloat16(q - __bfloat162float(h));
        float a = A[i];
        __nv_bfloat16 h2 = __float2bfloat16(a);
        g_ahi[i] = h2;
        g_alo[i] = __float2bfloat16(a - __bfloat162float(h2));
    }
}

// -------------------- main: fused GEMM + softmax-ratio + argmax --------------------
extern "C" __global__ void __launch_bounds__(NTH, 1)
mpl_main(const int* __restrict__ qid, const float* __restrict__ rnk, int B) {
    extern __shared__ __align__(128) char sm[];
    const uint32_t smb = su32(sm);
    const int tid = threadIdx.x, wid = tid >> 5, l = tid & 31;
    const int wm = wid >> 2, wn = wid & 3;      // 2x4 warp grid
    const int rowbase = blockIdx.x * ROWT;
    const int chunk = blockIdx.y;
    const int gcl = B / CHUNKS;
    const int gc0 = chunk * gcl;
    const int NT = gcl / COLT;

    // prologue: Q hi/lo + A tile 0 + meta 0
    for (int i = tid; i < 2048; i += NTH) {
        int r = i >> 4, cc = i & 15;
        int off = toff(r, cc);
        size_t g = (size_t)(rowbase + r) * DD + cc * 8;
        cpa16(smb + SM_QHI + off, g_qhi + g);
        cpa16(smb + SM_QLO + off, g_qlo + g);
    }
    load_a(smb, 0, gc0);
    load_meta(smb, 0, gc0, qid, rnk);
    cpcommit();

    // per-thread ldmatrix constants
    const int x = l & 7;
    const int subA = l >> 4;
    const int subB = (l >> 3) & 1;
    int rAoff[4], rBoff[4];
    #pragma unroll
    for (int mi = 0; mi < 4; mi++) rAoff[mi] = (wm * 64 + mi * 16 + (l & 15)) * 128;
    #pragma unroll
    for (int ni = 0; ni < 4; ni++) rBoff[ni] = (wn * 32 + ni * 8 + (l & 7)) * 128;

    int qrow[8];
    #pragma unroll
    for (int mi = 0; mi < 4; mi++)
        #pragma unroll
        for (int h = 0; h < 2; h++)
            qrow[mi * 2 + h] = qid[rowbase + wm * 64 + mi * 16 + (l >> 2) + h * 8];

    float den[8], num[8], mx[8];
    int   idx[8], cor[8];
    #pragma unroll
    for (int ri = 0; ri < 8; ri++) {
        den[ri] = 0.f; num[ri] = 0.f; mx[ri] = -3.4e38f;
        idx[ri] = 0x7fffffff; cor[ri] = 0;
    }

    cpwait0();
    __syncthreads();

    for (int t = 0; t < NT; t++) {
        const int b = t & 1;
        if (t + 1 < NT) {                       // prefetch next tile
            load_a(smb, b ^ 1, gc0 + (t + 1) * COLT);
            load_meta(smb, b ^ 1, gc0 + (t + 1) * COLT, qid, rnk);
            cpcommit();
        }

        float acc[4][4][4];
        #pragma unroll
        for (int mi = 0; mi < 4; mi++)
            #pragma unroll
            for (int ni = 0; ni < 4; ni++)
                #pragma unroll
                for (int k = 0; k < 4; k++) acc[mi][ni][k] = 0.f;

        const uint32_t smq = smb + SM_QHI;
        const uint32_t sma = smb + SM_A(b);

        #pragma unroll
        for (int s = 0; s < 8; s++) {
            const int ha = (s >> 2) << 14;
            const int cb = (s & 3) << 1;
            const int tA = (((cb | subA) ^ x) << 4) + ha;
            const int tB = (((cb | subB) ^ x) << 4) + ha;
            uint32_t ah[4][4], al[4][4], bh[4][2], bl[4][2];
            #pragma unroll
            for (int mi = 0; mi < 4; mi++) {
                uint32_t ad = smq + rAoff[mi] + tA;
                LDSM4(ah[mi], ad);
                LDSM4(al[mi], ad + 32768);
            }
            #pragma unroll
            for (int ni = 0; ni < 4; ni++) {
                uint32_t bd = sma + rBoff[ni] + tB;
                LDSM2(bh[ni], bd);
                LDSM2(bl[ni], bd + 32768);
            }
            #pragma unroll
            for (int mi = 0; mi < 4; mi++)
                #pragma unroll
                for (int ni = 0; ni < 4; ni++) {
                    MMA(acc[mi][ni], ah[mi], bh[ni]);   // hi*hi
                    MMA(acc[mi][ni], ah[mi], bl[ni]);   // hi*lo
                    MMA(acc[mi][ni], al[mi], bh[ni]);   // lo*hi
                }
        }

        // ---- fused epilogue (register-resident accs) ----
        const int*   idsb = (const int*)(sm + SM_IDS(b));
        const float* rkb  = (const float*)(sm + SM_RNK(b));
        int ids8[8], cg8[8];
        float w8[8];
        #pragma unroll
        for (int ni = 0; ni < 4; ni++)
            #pragma unroll
            for (int j = 0; j < 2; j++) {
                int cl = wn * 32 + ni * 8 + (l & 3) * 2 + j;
                int cj = ni * 2 + j;
                ids8[cj] = idsb[cl];
                w8[cj]   = 1.0f - 0.1f * rkb[cl];
                cg8[cj]  = gc0 + t * COLT + cl;
            }
        #pragma unroll
        for (int mi = 0; mi < 4; mi++)
            #pragma unroll
            for (int h = 0; h < 2; h++) {
                const int ri = mi * 2 + h;
                #pragma unroll
                for (int ni = 0; ni < 4; ni++)
                    #pragma unroll
                    for (int j = 0; j < 2; j++) {
                        const int cj = ni * 2 + j;
                        float s = acc[mi][ni][h * 2 + j];
                        float e = __expf(s);
                        den[ri] += e;
                        bool same = (ids8[cj] == qrow[ri]);
                        num[ri] = fmaf(same ? w8[cj] : 0.0f, e, num[ri]);
                        if (s > mx[ri]) {
                            mx[ri] = s; idx[ri] = cg8[cj]; cor[ri] = same ? 1 : 0;
                        }
                    }
            }

        if (t + 1 < NT) cpwait0();
        __syncthreads();
    }

    // ---- reduce: lanes sharing rows (l&3), then 4 wn warps via smem ----
    #pragma unroll
    for (int ri = 0; ri < 8; ri++) {
        #pragma unroll
        for (int o = 1; o <= 2; o <<= 1) {
            float om = __shfl_xor_sync(0xffffffffu, mx[ri], o);
            float od = __shfl_xor_sync(0xffffffffu, den[ri], o);
            float on = __shfl_xor_sync(0xffffffffu, num[ri], o);
            int   oi = __shfl_xor_sync(0xffffffffu, idx[ri], o);
            int   oc = __shfl_xor_sync(0xffffffffu, cor[ri], o);
            den[ri] += od; num[ri] += on;
            if (om > mx[ri] || (om == mx[ri] && oi < idx[ri])) {
                mx[ri] = om; idx[ri] = oi; cor[ri] = oc;
            }
        }
    }

    float* sden = (float*)sm;                 // [4][128]
    float* snum = (float*)(sm + 2048);
    float* smx  = (float*)(sm + 4096);
    int*   sidx = (int*)(sm + 6144);
    int*   scor = (int*)(sm + 8192);

    if ((l & 3) == 0) {
        #pragma unroll
        for (int mi = 0; mi < 4; mi++)
            #pragma unroll
            for (int h = 0; h < 2; h++) {
                int ri = mi * 2 + h;
                int row = wm * 64 + mi * 16 + (l >> 2) + h * 8;
                sden[wn * 128 + row] = den[ri];
                snum[wn * 128 + row] = num[ri];
                smx [wn * 128 + row] = mx[ri];
                sidx[wn * 128 + row] = idx[ri];
                scor[wn * 128 + row] = cor[ri];
            }
    }
    __syncthreads();
    if (tid < 128) {
        float d = 0.f, n = 0.f, m = -3.4e38f;
        int ix = 0x7fffffff, c = 0;
        #pragma unroll
        for (int w = 0; w < 4; w++) {
            d += sden[w * 128 + tid];
            n += snum[w * 128 + tid];
            float mm = smx[w * 128 + tid];
            int   ii = sidx[w * 128 + tid];
            if (mm > m || (mm == m && ii < ix)) { m = mm; ix = ii; c = scor[w * 128 + tid]; }
        }
        int grow = rowbase + tid;
        g_pden[chunk][grow] = d;
        g_pnum[chunk][grow] = n;
        g_pm[chunk][grow]   = m;
        g_pidx[chunk][grow] = ix;
        g_pcorr[chunk][grow] = c;
    }
}

// -------------------- merge chunks + block reduce --------------------
extern "C" __global__ void mpl_merge(int B) {
    int row = blockIdx.x * 256 + threadIdx.x;
    float loss = 0.f;
    int corr = 0;
    if (row < B) {
        float den = 0.f, num = 0.f, m = -3.4e38f;
        int ix = 0x7fffffff;
        #pragma unroll
        for (int c = 0; c < CHUNKS; c++) {
            den += g_pden[c][row];
            num += g_pnum[c][row];
            float mc = g_pm[c][row];
            int   ii = g_pidx[c][row];
            if (mc > m || (mc == m && ii < ix)) { m = mc; ix = ii; corr = g_pcorr[c][row]; }
        }
        loss = -logf(num / den + 1e-8f);
    }
    __shared__ float sf[256];
    __shared__ int   si[256];
    sf[threadIdx.x] = loss;
    si[threadIdx.x] = corr;
    __syncthreads();
    for (int o = 128; o > 0; o >>= 1) {
        if (threadIdx.x < o) {
            sf[threadIdx.x] += sf[threadIdx.x + o];
            si[threadIdx.x] += si[threadIdx.x + o];
        }
        __syncthreads();
    }
    if (threadIdx.x == 0) {
        g_blkloss[blockIdx.x] = sf[0];
        g_blkcorr[blockIdx.x] = si[0];
    }
}

extern "C" __global__ void mpl_final(float* out, int B, int nblk, int osz) {
    if (threadIdx.x == 0) {
        float s = 0.f;
        int c = 0;
        for (int i = 0; i < nblk; i++) { s += g_blkloss[i]; c += g_blkcorr[i]; }
        out[0] = s / (float)B;
        if (osz > 1) out[1] = (float)c / (float)B;
    }
}

extern "C" void kernel_launch(void* const* d_in, const int* in_sizes, int n_in,
                              void* d_out, int out_size) {
    const float* Q   = (const float*)d_in[0];
    const float* A   = (const float*)d_in[1];
    const int*   qid = (const int*)d_in[2];
    const float* rnk = (const float*)d_in[3];
    const int B = in_sizes[2];
    const int n = B * DD;

    mpl_prep<<<(n + 255) / 256, 256>>>(Q, A, n);

    cudaFuncSetAttribute(mpl_main, cudaFuncAttributeMaxDynamicSharedMemorySize,
                         SMEM_TOTAL);
    mpl_main<<<dim3(B / ROWT, CHUNKS), NTH, SMEM_TOTAL>>>(qid, rnk, B);

    mpl_merge<<<B / 256, 256>>>(B);
    mpl_final<<<1, 32>>>((float*)d_out, B, B / 256, out_size);
}

// round 5
// speedup vs baseline: 3.3710x; 1.0692x over previous
#include <cuda_runtime.h>
#include <cuda_bf16.h>
#include <cstdint>

#define MAXB 8192
#define DD   128
#define ROWT 128
#define COLT 128
#define CHUNKS 2
#define NTH  256

// ---------------- global scratch (no allocations allowed) ----------------
__device__ __nv_bfloat16 g_qhi[MAXB * DD], g_qlo[MAXB * DD];
__device__ __nv_bfloat16 g_ahi[MAXB * DD], g_alo[MAXB * DD];
__device__ float g_pden[CHUNKS][MAXB], g_pnum[CHUNKS][MAXB];
__device__ float g_pemax[CHUNKS][MAXB], g_pemp[CHUNKS][MAXB];

// ---------------- smem layout (dynamic) ----------------
// Qhi[32K] Qlo[32K]  A[2 bufs][hi 32K | lo 32K]  ids[2][512] rnk[2][512]
#define SM_QHI   0
#define SM_QLO   32768
#define SM_A(b)  (65536 + (b) * 65536)
#define SM_IDS(b) (196608 + (b) * 512)
#define SM_RNK(b) (197632 + (b) * 512)
#define SMEM_TOTAL 198656

static __device__ __forceinline__ unsigned su32(const void* p) {
    return (unsigned)__cvta_generic_to_shared(p);
}
static __device__ __forceinline__ void cpa16(unsigned d, const void* s) {
    asm volatile("cp.async.cg.shared.global [%0], [%1], 16;" :: "r"(d), "l"(s));
}
static __device__ __forceinline__ void cpcommit() {
    asm volatile("cp.async.commit_group;");
}
static __device__ __forceinline__ void cpwait0() {
    asm volatile("cp.async.wait_group 0;");
}
static __device__ __forceinline__ float ex2f(float x) {
    float r;
    asm("ex2.approx.ftz.f32 %0, %1;" : "=f"(r) : "f"(x));
    return r;
}

// SW128-atom tile offset for a 128-row x 128-bf16 (256B-wide logical) tile,
// stored as two 128B halves: half = cc>>3 (k 0..63 | 64..127)
static __device__ __forceinline__ int toff(int r, int cc) {   // cc = 16B chunk 0..15
    return ((cc >> 3) << 14) + r * 128 + (((cc & 7) ^ (r & 7)) << 4);
}

#define LDSM4(rg, ad) asm volatile( \
    "ldmatrix.sync.aligned.m8n8.x4.shared.b16 {%0,%1,%2,%3}, [%4];" \
    : "=r"((rg)[0]), "=r"((rg)[1]), "=r"((rg)[2]), "=r"((rg)[3]) : "r"(ad))
#define MMA(dd, aa, bb) asm volatile( \
    "mma.sync.aligned.m16n8k16.row.col.f32.bf16.bf16.f32 " \
    "{%0,%1,%2,%3}, {%4,%5,%6,%7}, {%8,%9}, {%0,%1,%2,%3};" \
    : "+f"((dd)[0]), "+f"((dd)[1]), "+f"((dd)[2]), "+f"((dd)[3]) \
    : "r"((aa)[0]), "r"((aa)[1]), "r"((aa)[2]), "r"((aa)[3]), \
      "r"((bb)[0]), "r"((bb)[1]))

static __device__ __forceinline__ void load_a(uint32_t smb, int b, int gcol0) {
    for (int i = threadIdx.x; i < 2048; i += NTH) {
        int r = i >> 4, cc = i & 15;
        int off = toff(r, cc);
        size_t g = (size_t)(gcol0 + r) * DD + cc * 8;
        cpa16(smb + SM_A(b) + off, g_ahi + g);
        cpa16(smb + SM_A(b) + 32768 + off, g_alo + g);
    }
}
static __device__ __forceinline__ void load_meta(uint32_t smb, int b, int gcol0,
                                                 const int* qid, const float* rnk) {
    int t = threadIdx.x;
    if (t < 32) {
        cpa16(smb + SM_IDS(b) + t * 16, qid + gcol0 + t * 4);
        cpa16(smb + SM_RNK(b) + t * 16, rnk + gcol0 + t * 4);
    }
}

// ---------- prep: fp32 -> bf16 hi/lo split (Q prescaled by log2(e)) ----------
extern "C" __global__ void mpl_prep(const float* __restrict__ Q,
                                    const float* __restrict__ A, int n) {
    int i = blockIdx.x * blockDim.x + threadIdx.x;
    if (i < n) {
        float q = Q[i] * 1.4426950408889634f;   // fold log2e into the GEMM
        __nv_bfloat16 h = __float2bfloat16(q);
        g_qhi[i] = h;
        g_qlo[i] = __float2bfloat16(q - __bfloat162float(h));
        float a = A[i];
        __nv_bfloat16 h2 = __float2bfloat16(a);
        g_ahi[i] = h2;
        g_alo[i] = __float2bfloat16(a - __bfloat162float(h2));
    }
}

// -------------------- main: fused GEMM + softmax-ratio --------------------
extern "C" __global__ void __launch_bounds__(NTH, 1)
mpl_main(const int* __restrict__ qid, const float* __restrict__ rnk, int B) {
    extern __shared__ __align__(128) char sm[];
    const uint32_t smb = su32(sm);
    const int tid = threadIdx.x, wid = tid >> 5, l = tid & 31;
    const int wm = wid >> 2, wn = wid & 3;      // 2x4 warp grid
    const int rowbase = blockIdx.x * ROWT;
    const int chunk = blockIdx.y;
    const int gcl = B / CHUNKS;
    const int gc0 = chunk * gcl;
    const int NT = gcl / COLT;

    // prologue: Q hi/lo + A tile 0 + meta 0
    for (int i = tid; i < 2048; i += NTH) {
        int r = i >> 4, cc = i & 15;
        int off = toff(r, cc);
        size_t g = (size_t)(rowbase + r) * DD + cc * 8;
        cpa16(smb + SM_QHI + off, g_qhi + g);
        cpa16(smb + SM_QLO + off, g_qlo + g);
    }
    load_a(smb, 0, gc0);
    load_meta(smb, 0, gc0, qid, rnk);
    cpcommit();

    // per-thread ldmatrix constants
    const int x = l & 7;
    const int subA = l >> 4;
    const int subB = (l >> 3) & 1;
    int rAoff[4], rBoff[2];
    #pragma unroll
    for (int mi = 0; mi < 4; mi++) rAoff[mi] = (wm * 64 + mi * 16 + (l & 15)) * 128;
    #pragma unroll
    for (int n2 = 0; n2 < 2; n2++)
        rBoff[n2] = (wn * 32 + n2 * 16 + ((l >> 4) << 3) + (l & 7)) * 128;

    int qrow[8];
    #pragma unroll
    for (int mi = 0; mi < 4; mi++)
        #pragma unroll
        for (int h = 0; h < 2; h++)
            qrow[mi * 2 + h] = qid[rowbase + wm * 64 + mi * 16 + (l >> 2) + h * 8];

    float den[8], num[8], emax[8], emp[8];
    #pragma unroll
    for (int ri = 0; ri < 8; ri++) {
        den[ri] = 0.f; num[ri] = 0.f; emax[ri] = 0.f; emp[ri] = 0.f;
    }

    cpwait0();
    __syncthreads();

    for (int t = 0; t < NT; t++) {
        const int b = t & 1;
        if (t + 1 < NT) {                       // prefetch next tile
            load_a(smb, b ^ 1, gc0 + (t + 1) * COLT);
            load_meta(smb, b ^ 1, gc0 + (t + 1) * COLT, qid, rnk);
            cpcommit();
        }

        float acc[4][4][4];
        #pragma unroll
        for (int mi = 0; mi < 4; mi++)
            #pragma unroll
            for (int ni = 0; ni < 4; ni++)
                #pragma unroll
                for (int k = 0; k < 4; k++) acc[mi][ni][k] = 0.f;

        const uint32_t smq = smb + SM_QHI;
        const uint32_t sma = smb + SM_A(b);

        #pragma unroll
        for (int s = 0; s < 8; s++) {
            const int ha = (s >> 2) << 14;
            const int cb = (s & 3) << 1;
            const int tA = (((cb | subA) ^ x) << 4) + ha;
            const int tB = (((cb | subB) ^ x) << 4) + ha;
            uint32_t ah[4][4], al[4][4], bh[2][4], bl[2][4];
            #pragma unroll
            for (int mi = 0; mi < 4; mi++) {
                uint32_t ad = smq + rAoff[mi] + tA;
                LDSM4(ah[mi], ad);
                LDSM4(al[mi], ad + 32768);
            }
            #pragma unroll
            for (int n2 = 0; n2 < 2; n2++) {
                uint32_t bd = sma + rBoff[n2] + tB;
                LDSM4(bh[n2], bd);          // {n2*16..+7, n2*16+8..+15} frags
                LDSM4(bl[n2], bd + 32768);
            }
            #pragma unroll
            for (int mi = 0; mi < 4; mi++)
                #pragma unroll
                for (int ni = 0; ni < 4; ni++) {
                    const uint32_t* bhf = &bh[ni >> 1][(ni & 1) * 2];
                    const uint32_t* blf = &bl[ni >> 1][(ni & 1) * 2];
                    MMA(acc[mi][ni], ah[mi], bhf);   // hi*hi
                    MMA(acc[mi][ni], ah[mi], blf);   // hi*lo
                    MMA(acc[mi][ni], al[mi], bhf);   // lo*hi
                }
        }

        // ---- fused epilogue (register-resident accs) ----
        const int*   idsb = (const int*)(sm + SM_IDS(b));
        const float* rkb  = (const float*)(sm + SM_RNK(b));
        int ids8[8];
        float w8[8];
        #pragma unroll
        for (int ni = 0; ni < 4; ni++)
            #pragma unroll
            for (int j = 0; j < 2; j++) {
                int cl = wn * 32 + ni * 8 + (l & 3) * 2 + j;
                ids8[ni * 2 + j] = idsb[cl];
                w8[ni * 2 + j]   = 1.0f - 0.1f * rkb[cl];
            }
        #pragma unroll
        for (int mi = 0; mi < 4; mi++)
            #pragma unroll
            for (int h = 0; h < 2; h++) {
                const int ri = mi * 2 + h;
                #pragma unroll
                for (int ni = 0; ni < 4; ni++)
                    #pragma unroll
                    for (int j = 0; j < 2; j++) {
                        const int cj = ni * 2 + j;
                        float e = ex2f(acc[mi][ni][h * 2 + j]);
                        den[ri] += e;
                        float em = (ids8[cj] == qrow[ri]) ? e : 0.0f;
                        num[ri] = fmaf(w8[cj], em, num[ri]);
                        emax[ri] = fmaxf(emax[ri], e);
                        emp[ri]  = fmaxf(emp[ri], em);
                    }
            }

        if (t + 1 < NT) cpwait0();
        __syncthreads();
    }

    // ---- reduce: lanes sharing rows (l&3), then 4 wn warps via smem ----
    #pragma unroll
    for (int ri = 0; ri < 8; ri++) {
        #pragma unroll
        for (int o = 1; o <= 2; o <<= 1) {
            den[ri]  += __shfl_xor_sync(0xffffffffu, den[ri], o);
            num[ri]  += __shfl_xor_sync(0xffffffffu, num[ri], o);
            emax[ri]  = fmaxf(emax[ri], __shfl_xor_sync(0xffffffffu, emax[ri], o));
            emp[ri]   = fmaxf(emp[ri],  __shfl_xor_sync(0xffffffffu, emp[ri],  o));
        }
    }

    float* sden = (float*)sm;                 // [4][128] each
    float* snum = (float*)(sm + 2048);
    float* smx  = (float*)(sm + 4096);
    float* smp  = (float*)(sm + 6144);

    if ((l & 3) == 0) {
        #pragma unroll
        for (int mi = 0; mi < 4; mi++)
            #pragma unroll
            for (int h = 0; h < 2; h++) {
                int ri = mi * 2 + h;
                int row = wm * 64 + mi * 16 + (l >> 2) + h * 8;
                sden[wn * 128 + row] = den[ri];
                snum[wn * 128 + row] = num[ri];
                smx [wn * 128 + row] = emax[ri];
                smp [wn * 128 + row] = emp[ri];
            }
    }
    __syncthreads();
    if (tid < 128) {
        float d = 0.f, n = 0.f, mx = 0.f, mp = 0.f;
        #pragma unroll
        for (int w = 0; w < 4; w++) {
            d += sden[w * 128 + tid];
            n += snum[w * 128 + tid];
            mx = fmaxf(mx, smx[w * 128 + tid]);
            mp = fmaxf(mp, smp[w * 128 + tid]);
        }
        int grow = rowbase + tid;
        g_pden[chunk][grow]  = d;
        g_pnum[chunk][grow]  = n;
        g_pemax[chunk][grow] = mx;
        g_pemp[chunk][grow]  = mp;
    }
}

// -------------------- tail: merge chunks + final reduce (one block) --------------------
extern "C" __global__ void mpl_tail(float* out, int B, int osz) {
    const int tid = threadIdx.x;
    float ls = 0.f;
    int cs = 0;
    for (int r = tid; r < B; r += 1024) {
        float d = 0.f, n = 0.f, mx = 0.f, mp = 0.f;
        #pragma unroll
        for (int c = 0; c < CHUNKS; c++) {
            d += g_pden[c][r];
            n += g_pnum[c][r];
            mx = fmaxf(mx, g_pemax[c][r]);
            mp = fmaxf(mp, g_pemp[c][r]);
        }
        ls += -logf(n / d + 1e-8f);
        cs += (mp >= mx) ? 1 : 0;     // argmax column is a positive
    }
    __shared__ float sf[1024];
    __shared__ int   si[1024];
    sf[tid] = ls; si[tid] = cs;
    __syncthreads();
    for (int o = 512; o > 0; o >>= 1) {
        if (tid < o) { sf[tid] += sf[tid + o]; si[tid] += si[tid + o]; }
        __syncthreads();
    }
    if (tid == 0) {
        out[0] = sf[0] / (float)B;
        if (osz > 1) out[1] = (float)si[0] / (float)B;
    }
}

extern "C" void kernel_launch(void* const* d_in, const int* in_sizes, int n_in,
                              void* d_out, int out_size) {
    const float* Q   = (const float*)d_in[0];
    const float* A   = (const float*)d_in[1];
    const int*   qid = (const int*)d_in[2];
    const float* rnk = (const float*)d_in[3];
    const int B = in_sizes[2];
    const int n = B * DD;

    mpl_prep<<<(n + 255) / 256, 256>>>(Q, A, n);

    cudaFuncSetAttribute(mpl_main, cudaFuncAttributeMaxDynamicSharedMemorySize,
                         SMEM_TOTAL);
    mpl_main<<<dim3(B / ROWT, CHUNKS), NTH, SMEM_TOTAL>>>(qid, rnk, B);

    mpl_tail<<<1, 1024>>>((float*)d_out, B, out_size);
}

// round 6
// speedup vs baseline: 3.7916x; 1.1248x over previous
#include <cuda_runtime.h>
#include <cuda_bf16.h>
#include <cstdint>

#define MAXB 8192
#define DD   128
#define NTH  256
#define NSM  148

// ---------------- global scratch (no allocations allowed) ----------------
__device__ __nv_bfloat16 g_qhi[MAXB * DD], g_qlo[MAXB * DD];
__device__ __nv_bfloat16 g_ahi[MAXB * DD], g_alo[MAXB * DD];
__device__ float g_den[MAXB], g_num[MAXB];
__device__ int   g_emax[MAXB], g_emp[MAXB];

// ---------------- smem layout ----------------
#define SM_QHI   0
#define SM_QLO   32768
#define SM_A(b)  (65536 + (b) * 65536)        // hi at +0, lo at +32768
#define SM_IDS(s) (196608 + (s) * 512)        // 4 slots
#define SM_RNK(s) (198656 + (s) * 512)        // 4 slots
#define SM_RED   200704                       // 8KB reduction area
#define SMEM_TOTAL 208896

static __device__ __forceinline__ unsigned su32(const void* p) {
    return (unsigned)__cvta_generic_to_shared(p);
}
static __device__ __forceinline__ void cpa16(unsigned d, const void* s) {
    asm volatile("cp.async.cg.shared.global [%0], [%1], 16;" :: "r"(d), "l"(s));
}
static __device__ __forceinline__ void cpcommit() {
    asm volatile("cp.async.commit_group;");
}
static __device__ __forceinline__ void cpwait0() {
    asm volatile("cp.async.wait_group 0;");
}
static __device__ __forceinline__ float ex2f(float x) {
    float r;
    asm("ex2.approx.ftz.f32 %0, %1;" : "=f"(r) : "f"(x));
    return r;
}

// SW128-atom tile offset: 128 rows x 128 bf16, two 128B k-halves
static __device__ __forceinline__ int toff(int r, int cc) {   // cc = 16B chunk 0..15
    return ((cc >> 3) << 14) + r * 128 + (((cc & 7) ^ (r & 7)) << 4);
}

#define LDSM4(rg, ad) asm volatile( \
    "ldmatrix.sync.aligned.m8n8.x4.shared.b16 {%0,%1,%2,%3}, [%4];" \
    : "=r"((rg)[0]), "=r"((rg)[1]), "=r"((rg)[2]), "=r"((rg)[3]) : "r"(ad))
#define MMAI(dd, aa, bb) asm volatile( \
    "mma.sync.aligned.m16n8k16.row.col.f32.bf16.bf16.f32 " \
    "{%0,%1,%2,%3}, {%4,%5,%6,%7}, {%8,%9}, {%0,%1,%2,%3};" \
    : "+f"((dd)[0]), "+f"((dd)[1]), "+f"((dd)[2]), "+f"((dd)[3]) \
    : "r"((aa)[0]), "r"((aa)[1]), "r"((aa)[2]), "r"((aa)[3]), \
      "r"((bb)[0]), "r"((bb)[1]))

static __device__ __forceinline__ void load_a(uint32_t smb, int buf, int gcol0) {
    for (int i = threadIdx.x; i < 2048; i += NTH) {
        int r = i >> 4, cc = i & 15;
        int off = toff(r, cc);
        size_t g = (size_t)(gcol0 + r) * DD + cc * 8;
        cpa16(smb + SM_A(buf) + off, g_ahi + g);
        cpa16(smb + SM_A(buf) + 32768 + off, g_alo + g);
    }
}
static __device__ __forceinline__ void load_meta(uint32_t smb, int slot, int gcol0,
                                                 const int* qid, const float* rnk) {
    int t = threadIdx.x;
    if (t < 32) {
        cpa16(smb + SM_IDS(slot) + t * 16, qid + gcol0 + t * 4);
        cpa16(smb + SM_RNK(slot) + t * 16, rnk + gcol0 + t * 4);
    }
}

// One tile: ldsm + 3-pass MMA into `cur`; epilogue of `prev` interleaved per s-step.
template<int DO_EP>
static __device__ __forceinline__ void tile_step(
    const char* sm, uint32_t smb, uint32_t sma, int prevslot,
    float (&cur)[4][4][4], float (&prev)[4][4][4],
    const int* qrow, float* den, float* num, float* emax, float* emp,
    int l, int wn, int x, int subA, int subB,
    const int* rAoff, const int* rBoff)
{
    #pragma unroll
    for (int mi = 0; mi < 4; mi++)
        #pragma unroll
        for (int ni = 0; ni < 4; ni++)
            #pragma unroll
            for (int k = 0; k < 4; k++) cur[mi][ni][k] = 0.f;

    int ids8[8];
    float w8[8];
    if (DO_EP) {
        const int*   idsb = (const int*)(sm + SM_IDS(prevslot));
        const float* rkb  = (const float*)(sm + SM_RNK(prevslot));
        #pragma unroll
        for (int ni = 0; ni < 4; ni++)
            #pragma unroll
            for (int jj = 0; jj < 2; jj++) {
                int cl = wn * 32 + ni * 8 + (l & 3) * 2 + jj;
                ids8[ni * 2 + jj] = idsb[cl];
                w8[ni * 2 + jj]   = 1.0f - 0.1f * rkb[cl];
            }
    }

    const uint32_t smq = smb + SM_QHI;
    #pragma unroll
    for (int s = 0; s < 8; s++) {
        const int ha = (s >> 2) << 14;
        const int cb = (s & 3) << 1;
        const int tA = (((cb | subA) ^ x) << 4) + ha;
        const int tB = (((cb | subB) ^ x) << 4) + ha;
        uint32_t ah[4][4], al[4][4], bh[2][4], bl[2][4];
        #pragma unroll
        for (int mi = 0; mi < 4; mi++) {
            uint32_t ad = smq + rAoff[mi] + tA;
            LDSM4(ah[mi], ad);
            LDSM4(al[mi], ad + 32768);
        }
        #pragma unroll
        for (int n2 = 0; n2 < 2; n2++) {
            uint32_t bd = sma + rBoff[n2] + tB;
            LDSM4(bh[n2], bd);
            LDSM4(bl[n2], bd + 32768);
        }
        #pragma unroll
        for (int mi = 0; mi < 4; mi++)
            #pragma unroll
            for (int ni = 0; ni < 4; ni++) {
                const uint32_t* bhf = &bh[ni >> 1][(ni & 1) * 2];
                const uint32_t* blf = &bl[ni >> 1][(ni & 1) * 2];
                MMAI(cur[mi][ni], ah[mi], bhf);   // hi*hi
                MMAI(cur[mi][ni], ah[mi], blf);   // hi*lo
                MMAI(cur[mi][ni], al[mi], bhf);   // lo*hi
            }
        if (DO_EP) {   // epilogue chunk s of previous tile (overlaps tensor pipe)
            const int mi = s >> 1, h = s & 1;
            #pragma unroll
            for (int ni = 0; ni < 4; ni++)
                #pragma unroll
                for (int jj = 0; jj < 2; jj++) {
                    const int cj = ni * 2 + jj;
                    float e = ex2f(prev[mi][ni][h * 2 + jj]);
                    den[s] += e;
                    float em = (ids8[cj] == qrow[s]) ? e : 0.0f;
                    num[s] = fmaf(w8[cj], em, num[s]);
                    emax[s] = fmaxf(emax[s], e);
                    emp[s]  = fmaxf(emp[s], em);
                }
        }
    }
}

// standalone epilogue (drain for the last tile of a segment)
static __device__ __forceinline__ void drain_ep(
    const char* sm, int slot, float (&prev)[4][4][4],
    const int* qrow, float* den, float* num, float* emax, float* emp,
    int l, int wn)
{
    const int*   idsb = (const int*)(sm + SM_IDS(slot));
    const float* rkb  = (const float*)(sm + SM_RNK(slot));
    int ids8[8];
    float w8[8];
    #pragma unroll
    for (int ni = 0; ni < 4; ni++)
        #pragma unroll
        for (int jj = 0; jj < 2; jj++) {
            int cl = wn * 32 + ni * 8 + (l & 3) * 2 + jj;
            ids8[ni * 2 + jj] = idsb[cl];
            w8[ni * 2 + jj]   = 1.0f - 0.1f * rkb[cl];
        }
    #pragma unroll
    for (int s = 0; s < 8; s++) {
        const int mi = s >> 1, h = s & 1;
        #pragma unroll
        for (int ni = 0; ni < 4; ni++)
            #pragma unroll
            for (int jj = 0; jj < 2; jj++) {
                const int cj = ni * 2 + jj;
                float e = ex2f(prev[mi][ni][h * 2 + jj]);
                den[s] += e;
                float em = (ids8[cj] == qrow[s]) ? e : 0.0f;
                num[s] = fmaf(w8[cj], em, num[s]);
                emax[s] = fmaxf(emax[s], e);
                emp[s]  = fmaxf(emp[s], em);
            }
    }
}

// ---------- prep: fp32 -> bf16 hi/lo split (Q prescaled by log2(e)) + zero-init ----------
extern "C" __global__ void mpl_prep(const float4* __restrict__ Q4,
                                    const float4* __restrict__ A4, int n4) {
    int i = blockIdx.x * blockDim.x + threadIdx.x;
    if (i < n4) {
        float4 q = Q4[i], a = A4[i];
        float qv[4] = {q.x, q.y, q.z, q.w}, av[4] = {a.x, a.y, a.z, a.w};
        __nv_bfloat162 qh[2], ql[2], ah[2], al[2];
        #pragma unroll
        for (int k = 0; k < 4; k++) {
            float qs = qv[k] * 1.4426950408889634f;
            __nv_bfloat16 h = __float2bfloat16(qs);
            __nv_bfloat16 lo = __float2bfloat16(qs - __bfloat162float(h));
            ((__nv_bfloat16*)qh)[k] = h;
            ((__nv_bfloat16*)ql)[k] = lo;
            __nv_bfloat16 h2 = __float2bfloat16(av[k]);
            __nv_bfloat16 lo2 = __float2bfloat16(av[k] - __bfloat162float(h2));
            ((__nv_bfloat16*)ah)[k] = h2;
            ((__nv_bfloat16*)al)[k] = lo2;
        }
        ((float2*)g_qhi)[i] = *(float2*)qh;
        ((float2*)g_qlo)[i] = *(float2*)ql;
        ((float2*)g_ahi)[i] = *(float2*)ah;
        ((float2*)g_alo)[i] = *(float2*)al;
    }
    if (i < MAXB) {
        g_den[i] = 0.f; g_num[i] = 0.f; g_emax[i] = 0; g_emp[i] = 0;
    }
}

// -------------------- main: balanced persistent fused GEMM + softmax-ratio --------------------
extern "C" __global__ void __launch_bounds__(NTH, 1)
mpl_main(const int* __restrict__ qid, const float* __restrict__ rnk, int B) {
    extern __shared__ __align__(128) char sm[];
    const uint32_t smb = su32(sm);
    const int tid = threadIdx.x, wid = tid >> 5, l = tid & 31;
    const int wm = wid >> 2, wn = wid & 3;
    const int ncol = B / 128, nrow = B / 128;
    const long long total = (long long)nrow * ncol;
    int start = (int)(total * blockIdx.x / NSM);
    int end   = (int)(total * (blockIdx.x + 1) / NSM);

    const int x = l & 7, subA = l >> 4, subB = (l >> 3) & 1;
    int rAoff[4], rBoff[2];
    #pragma unroll
    for (int mi = 0; mi < 4; mi++) rAoff[mi] = (wm * 64 + mi * 16 + (l & 15)) * 128;
    #pragma unroll
    for (int n2 = 0; n2 < 2; n2++)
        rBoff[n2] = (wn * 32 + n2 * 16 + ((l >> 4) << 3) + (l & 7)) * 128;

    float accA[4][4][4], accB[4][4][4];

    int pos = start;
    while (pos < end) {
        const int rt = pos / ncol;
        const int c0 = pos - rt * ncol;
        const int c1 = min(ncol, c0 + (end - pos));
        pos += c1 - c0;
        const int rowbase = rt * 128;

        // Q tile (hi/lo) + A(c0) + meta(c0), one group
        for (int i = tid; i < 2048; i += NTH) {
            int r = i >> 4, cc = i & 15;
            int off = toff(r, cc);
            size_t g = (size_t)(rowbase + r) * DD + cc * 8;
            cpa16(smb + SM_QHI + off, g_qhi + g);
            cpa16(smb + SM_QLO + off, g_qlo + g);
        }
        load_a(smb, c0 & 1, c0 * 128);
        load_meta(smb, c0 & 3, c0 * 128, qid, rnk);
        cpcommit();

        int qrow[8];
        #pragma unroll
        for (int mi = 0; mi < 4; mi++)
            #pragma unroll
            for (int h = 0; h < 2; h++)
                qrow[mi * 2 + h] = qid[rowbase + wm * 64 + mi * 16 + (l >> 2) + h * 8];

        float den[8], num[8], emax[8], emp[8];
        #pragma unroll
        for (int ri = 0; ri < 8; ri++) {
            den[ri] = 0.f; num[ri] = 0.f; emax[ri] = 0.f; emp[ri] = 0.f;
        }

        cpwait0();
        __syncthreads();

        for (int j = c0; j < c1; j++) {
            if (j + 1 < c1) {
                load_a(smb, (j + 1) & 1, (j + 1) * 128);
                load_meta(smb, (j + 1) & 3, (j + 1) * 128, qid, rnk);
                cpcommit();
            }
            const uint32_t sma = smb + SM_A(j & 1);
            const int ps = (j - 1) & 3;
            if (j > c0) {
                if (j & 1) tile_step<1>(sm, smb, sma, ps, accB, accA, qrow,
                                        den, num, emax, emp, l, wn, x, subA, subB, rAoff, rBoff);
                else       tile_step<1>(sm, smb, sma, ps, accA, accB, qrow,
                                        den, num, emax, emp, l, wn, x, subA, subB, rAoff, rBoff);
            } else {
                if (j & 1) tile_step<0>(sm, smb, sma, 0, accB, accA, qrow,
                                        den, num, emax, emp, l, wn, x, subA, subB, rAoff, rBoff);
                else       tile_step<0>(sm, smb, sma, 0, accA, accB, qrow,
                                        den, num, emax, emp, l, wn, x, subA, subB, rAoff, rBoff);
            }
            if (j + 1 < c1) cpwait0();
            __syncthreads();
        }
        {   // drain epilogue of last tile
            const int ps = (c1 - 1) & 3;
            if ((c1 - 1) & 1) drain_ep(sm, ps, accB, qrow, den, num, emax, emp, l, wn);
            else              drain_ep(sm, ps, accA, qrow, den, num, emax, emp, l, wn);
        }

        // ---- reduce: lane quads, then 4 wn warps via smem, then atomics ----
        #pragma unroll
        for (int ri = 0; ri < 8; ri++) {
            #pragma unroll
            for (int o = 1; o <= 2; o <<= 1) {
                den[ri]  += __shfl_xor_sync(0xffffffffu, den[ri], o);
                num[ri]  += __shfl_xor_sync(0xffffffffu, num[ri], o);
                emax[ri]  = fmaxf(emax[ri], __shfl_xor_sync(0xffffffffu, emax[ri], o));
                emp[ri]   = fmaxf(emp[ri],  __shfl_xor_sync(0xffffffffu, emp[ri],  o));
            }
        }
        float* sden = (float*)(sm + SM_RED);
        float* snum = (float*)(sm + SM_RED + 2048);
        float* smx  = (float*)(sm + SM_RED + 4096);
        float* smp  = (float*)(sm + SM_RED + 6144);
        if ((l & 3) == 0) {
            #pragma unroll
            for (int mi = 0; mi < 4; mi++)
                #pragma unroll
                for (int h = 0; h < 2; h++) {
                    int ri = mi * 2 + h;
                    int row = wm * 64 + mi * 16 + (l >> 2) + h * 8;
                    sden[wn * 128 + row] = den[ri];
                    snum[wn * 128 + row] = num[ri];
                    smx [wn * 128 + row] = emax[ri];
                    smp [wn * 128 + row] = emp[ri];
                }
        }
        __syncthreads();
        if (tid < 128) {
            float d = 0.f, n = 0.f, mx = 0.f, mp = 0.f;
            #pragma unroll
            for (int w = 0; w < 4; w++) {
                d += sden[w * 128 + tid];
                n += snum[w * 128 + tid];
                mx = fmaxf(mx, smx[w * 128 + tid]);
                mp = fmaxf(mp, smp[w * 128 + tid]);
            }
            atomicAdd(&g_den[rowbase + tid], d);
            atomicAdd(&g_num[rowbase + tid], n);
            atomicMax(&g_emax[rowbase + tid], __float_as_int(mx));
            atomicMax(&g_emp[rowbase + tid], __float_as_int(mp));
        }
        __syncthreads();
    }
}

// -------------------- tail: loss + accuracy (one block) --------------------
extern "C" __global__ void mpl_tail(float* out, int B, int osz) {
    const int tid = threadIdx.x;
    float ls = 0.f;
    int cs = 0;
    for (int r = tid; r < B; r += 1024) {
        float d = g_den[r], n = g_num[r];
        float mx = __int_as_float(g_emax[r]);
        float mp = __int_as_float(g_emp[r]);
        ls += -logf(n / d + 1e-8f);
        cs += (mp >= mx) ? 1 : 0;
    }
    __shared__ float sf[1024];
    __shared__ int   si[1024];
    sf[tid] = ls; si[tid] = cs;
    __syncthreads();
    for (int o = 512; o > 0; o >>= 1) {
        if (tid < o) { sf[tid] += sf[tid + o]; si[tid] += si[tid + o]; }
        __syncthreads();
    }
    if (tid == 0) {
        out[0] = sf[0] / (float)B;
        if (osz > 1) out[1] = (float)si[0] / (float)B;
    }
}

extern "C" void kernel_launch(void* const* d_in, const int* in_sizes, int n_in,
                              void* d_out, int out_size) {
    const float* Q   = (const float*)d_in[0];
    const float* A   = (const float*)d_in[1];
    const int*   qid = (const int*)d_in[2];
    const float* rnk = (const float*)d_in[3];
    const int B = in_sizes[2];
    const int n4 = B * DD / 4;

    mpl_prep<<<(n4 + 255) / 256, 256>>>((const float4*)Q, (const float4*)A, n4);

    cudaFuncSetAttribute(mpl_main, cudaFuncAttributeMaxDynamicSharedMemorySize,
                         SMEM_TOTAL);
    mpl_main<<<NSM, NTH, SMEM_TOTAL>>>(qid, rnk, B);

    mpl_tail<<<1, 1024>>>((float*)d_out, B, out_size);
}

// round 7
// speedup vs baseline: 3.8432x; 1.0136x over previous
#include <cuda_runtime.h>
#include <cuda_bf16.h>
#include <cstdint>

#define MAXB 8192
#define DD   128
#define NTH  256
#define NSM  148
#define ROWT 256
#define COLT 64

// ---------------- global scratch (no allocations allowed) ----------------
__device__ __nv_bfloat16 g_qhi[MAXB * DD], g_qlo[MAXB * DD];
__device__ __nv_bfloat16 g_ahi[MAXB * DD], g_alo[MAXB * DD];
__device__ float g_den[MAXB], g_num[MAXB];
__device__ int   g_emax[MAXB], g_emp[MAXB];

// ---------------- smem layout ----------------
// Q: 256 rows, k-halves of 32KB each (hi), same for lo. A: 64 rows, k-halves 8KB.
#define SM_QHI   0                       // 64KB
#define SM_QLO   65536                   // 64KB
#define SM_A(b)  (131072 + (b) * 32768)  // hi +0 (16KB), lo +16384
#define SM_IDS(s) (196608 + (s) * 256)   // 4 slots x 64 ids
#define SM_RNK(s) (197632 + (s) * 256)   // 4 slots x 64 ranks
#define SM_RED   198656                  // 8KB reduction area
#define SMEM_TOTAL 206848

static __device__ __forceinline__ unsigned su32(const void* p) {
    return (unsigned)__cvta_generic_to_shared(p);
}
static __device__ __forceinline__ void cpa16(unsigned d, const void* s) {
    asm volatile("cp.async.cg.shared.global [%0], [%1], 16;" :: "r"(d), "l"(s));
}
static __device__ __forceinline__ void cpcommit() {
    asm volatile("cp.async.commit_group;");
}
static __device__ __forceinline__ void cpwait0() {
    asm volatile("cp.async.wait_group 0;");
}
static __device__ __forceinline__ float ex2f(float x) {
    float r;
    asm("ex2.approx.ftz.f32 %0, %1;" : "=f"(r) : "f"(x));
    return r;
}

// swizzled offset inside one k-half region (row r, 16B chunk c within half 0..7)
static __device__ __forceinline__ int halfoff(int r, int c) {
    return r * 128 + ((c ^ (r & 7)) << 4);
}

#define LDSM4(rg, ad) asm volatile( \
    "ldmatrix.sync.aligned.m8n8.x4.shared.b16 {%0,%1,%2,%3}, [%4];" \
    : "=r"((rg)[0]), "=r"((rg)[1]), "=r"((rg)[2]), "=r"((rg)[3]) : "r"(ad))
#define MMAI(dd, aa, bb) asm volatile( \
    "mma.sync.aligned.m16n8k16.row.col.f32.bf16.bf16.f32 " \
    "{%0,%1,%2,%3}, {%4,%5,%6,%7}, {%8,%9}, {%0,%1,%2,%3};" \
    : "+f"((dd)[0]), "+f"((dd)[1]), "+f"((dd)[2]), "+f"((dd)[3]) \
    : "r"((aa)[0]), "r"((aa)[1]), "r"((aa)[2]), "r"((aa)[3]), \
      "r"((bb)[0]), "r"((bb)[1]))

// A (answer) tile: 64 rows x 128 bf16, hi+lo, k-half stride 8192
static __device__ __forceinline__ void load_a(uint32_t smb, int buf, int gcol0) {
    for (int i = threadIdx.x; i < 1024; i += NTH) {
        int r = i >> 4, cc = i & 15;
        int off = ((cc >> 3) << 13) + halfoff(r, cc & 7);
        size_t g = (size_t)(gcol0 + r) * DD + cc * 8;
        cpa16(smb + SM_A(buf) + off, g_ahi + g);
        cpa16(smb + SM_A(buf) + 16384 + off, g_alo + g);
    }
}
static __device__ __forceinline__ void load_meta(uint32_t smb, int slot, int gcol0,
                                                 const int* qid, const float* rnk) {
    int t = threadIdx.x;
    if (t < 16) {
        cpa16(smb + SM_IDS(slot) + t * 16, qid + gcol0 + t * 4);
        cpa16(smb + SM_RNK(slot) + t * 16, rnk + gcol0 + t * 4);
    }
}

// One tile: ldsm + 3-pass MMA into `cur`; epilogue of `prev` interleaved per s-step.
template<int DO_EP>
static __device__ __forceinline__ void tile_step(
    const char* sm, uint32_t smb, uint32_t sma, int prevslot,
    float (&cur)[4][4][4], float (&prev)[4][4][4],
    const int* qrow, float* den, float* num, float* emax, float* emp,
    int l, int wn, int x, int subA, int subB,
    const int* rAoff, const int* rBoff)
{
    #pragma unroll
    for (int mi = 0; mi < 4; mi++)
        #pragma unroll
        for (int ni = 0; ni < 4; ni++)
            #pragma unroll
            for (int k = 0; k < 4; k++) cur[mi][ni][k] = 0.f;

    int ids8[8];
    float w8[8];
    if (DO_EP) {
        const int*   idsb = (const int*)(sm + SM_IDS(prevslot));
        const float* rkb  = (const float*)(sm + SM_RNK(prevslot));
        #pragma unroll
        for (int ni = 0; ni < 4; ni++)
            #pragma unroll
            for (int jj = 0; jj < 2; jj++) {
                int cl = wn * 32 + ni * 8 + (l & 3) * 2 + jj;
                ids8[ni * 2 + jj] = idsb[cl];
                w8[ni * 2 + jj]   = 1.0f - 0.1f * rkb[cl];
            }
    }

    const uint32_t smq = smb + SM_QHI;
    #pragma unroll
    for (int s = 0; s < 8; s++) {
        const int haQ = (s >> 2) << 15;          // Q k-half stride 32KB
        const int haA = (s >> 2) << 13;          // A k-half stride 8KB
        const int cb = (s & 3) << 1;
        const int tA = (((cb | subA) ^ x) << 4) + haQ;
        const int tB = (((cb | subB) ^ x) << 4) + haA;
        uint32_t ah[4][4], al[4][4], bh[2][4], bl[2][4];
        #pragma unroll
        for (int mi = 0; mi < 4; mi++) {
            uint32_t ad = smq + rAoff[mi] + tA;
            LDSM4(ah[mi], ad);
            LDSM4(al[mi], ad + 65536);           // Qlo region
        }
        #pragma unroll
        for (int n2 = 0; n2 < 2; n2++) {
            uint32_t bd = sma + rBoff[n2] + tB;
            LDSM4(bh[n2], bd);
            LDSM4(bl[n2], bd + 16384);           // A lo region
        }
        #pragma unroll
        for (int mi = 0; mi < 4; mi++)
            #pragma unroll
            for (int ni = 0; ni < 4; ni++) {
                const uint32_t* bhf = &bh[ni >> 1][(ni & 1) * 2];
                const uint32_t* blf = &bl[ni >> 1][(ni & 1) * 2];
                MMAI(cur[mi][ni], ah[mi], bhf);   // hi*hi
                MMAI(cur[mi][ni], ah[mi], blf);   // hi*lo
                MMAI(cur[mi][ni], al[mi], bhf);   // lo*hi
            }
        if (DO_EP) {   // epilogue chunk s of previous tile (overlaps tensor pipe)
            const int mi = s >> 1, h = s & 1;
            #pragma unroll
            for (int ni = 0; ni < 4; ni++)
                #pragma unroll
                for (int jj = 0; jj < 2; jj++) {
                    const int cj = ni * 2 + jj;
                    float e = ex2f(prev[mi][ni][h * 2 + jj]);
                    den[s] += e;
                    float em = (ids8[cj] == qrow[s]) ? e : 0.0f;
                    num[s] = fmaf(w8[cj], em, num[s]);
                    emax[s] = fmaxf(emax[s], e);
                    emp[s]  = fmaxf(emp[s], em);
                }
        }
    }
}

// standalone epilogue (drain for the last tile of a segment)
static __device__ __forceinline__ void drain_ep(
    const char* sm, int slot, float (&prev)[4][4][4],
    const int* qrow, float* den, float* num, float* emax, float* emp,
    int l, int wn)
{
    const int*   idsb = (const int*)(sm + SM_IDS(slot));
    const float* rkb  = (const float*)(sm + SM_RNK(slot));
    int ids8[8];
    float w8[8];
    #pragma unroll
    for (int ni = 0; ni < 4; ni++)
        #pragma unroll
        for (int jj = 0; jj < 2; jj++) {
            int cl = wn * 32 + ni * 8 + (l & 3) * 2 + jj;
            ids8[ni * 2 + jj] = idsb[cl];
            w8[ni * 2 + jj]   = 1.0f - 0.1f * rkb[cl];
        }
    #pragma unroll
    for (int s = 0; s < 8; s++) {
        const int mi = s >> 1, h = s & 1;
        #pragma unroll
        for (int ni = 0; ni < 4; ni++)
            #pragma unroll
            for (int jj = 0; jj < 2; jj++) {
                const int cj = ni * 2 + jj;
                float e = ex2f(prev[mi][ni][h * 2 + jj]);
                den[s] += e;
                float em = (ids8[cj] == qrow[s]) ? e : 0.0f;
                num[s] = fmaf(w8[cj], em, num[s]);
                emax[s] = fmaxf(emax[s], e);
                emp[s]  = fmaxf(emp[s], em);
            }
    }
}

// ---------- prep: fp32 -> bf16 hi/lo split (Q prescaled by log2(e)) + zero-init ----------
extern "C" __global__ void mpl_prep(const float4* __restrict__ Q4,
                                    const float4* __restrict__ A4, int n4) {
    int i = blockIdx.x * blockDim.x + threadIdx.x;
    if (i < n4) {
        float4 q = Q4[i], a = A4[i];
        float qv[4] = {q.x, q.y, q.z, q.w}, av[4] = {a.x, a.y, a.z, a.w};
        __nv_bfloat162 qh[2], ql[2], ah[2], al[2];
        #pragma unroll
        for (int k = 0; k < 4; k++) {
            float qs = qv[k] * 1.4426950408889634f;
            __nv_bfloat16 h = __float2bfloat16(qs);
            __nv_bfloat16 lo = __float2bfloat16(qs - __bfloat162float(h));
            ((__nv_bfloat16*)qh)[k] = h;
            ((__nv_bfloat16*)ql)[k] = lo;
            __nv_bfloat16 h2 = __float2bfloat16(av[k]);
            __nv_bfloat16 lo2 = __float2bfloat16(av[k] - __bfloat162float(h2));
            ((__nv_bfloat16*)ah)[k] = h2;
            ((__nv_bfloat16*)al)[k] = lo2;
        }
        ((float2*)g_qhi)[i] = *(float2*)qh;
        ((float2*)g_qlo)[i] = *(float2*)ql;
        ((float2*)g_ahi)[i] = *(float2*)ah;
        ((float2*)g_alo)[i] = *(float2*)al;
    }
    if (i < MAXB) {
        g_den[i] = 0.f; g_num[i] = 0.f; g_emax[i] = 0; g_emp[i] = 0;
    }
}

// -------------------- main: balanced persistent fused GEMM + softmax-ratio --------------------
extern "C" __global__ void __launch_bounds__(NTH, 1)
mpl_main(const int* __restrict__ qid, const float* __restrict__ rnk, int B) {
    extern __shared__ __align__(128) char sm[];
    const uint32_t smb = su32(sm);
    const int tid = threadIdx.x, wid = tid >> 5, l = tid & 31;
    const int wm = wid >> 1, wn = wid & 1;       // 4x2 warp grid (64x32 per warp)
    const int ncol = B / COLT, nrow = B / ROWT;
    const long long total = (long long)nrow * ncol;
    int start = (int)(total * blockIdx.x / NSM);
    int end   = (int)(total * (blockIdx.x + 1) / NSM);

    const int x = l & 7, subA = l >> 4, subB = (l >> 3) & 1;
    int rAoff[4], rBoff[2];
    #pragma unroll
    for (int mi = 0; mi < 4; mi++) rAoff[mi] = (wm * 64 + mi * 16 + (l & 15)) * 128;
    #pragma unroll
    for (int n2 = 0; n2 < 2; n2++)
        rBoff[n2] = (wn * 32 + n2 * 16 + ((l >> 4) << 3) + (l & 7)) * 128;

    float accA[4][4][4], accB[4][4][4];

    int pos = start;
    while (pos < end) {
        const int rt = pos / ncol;
        const int c0 = pos - rt * ncol;
        const int c1 = min(ncol, c0 + (end - pos));
        pos += c1 - c0;
        const int rowbase = rt * ROWT;

        // Q tile (256 rows, hi/lo) + A(c0) + meta(c0), one group
        for (int i = tid; i < 4096; i += NTH) {
            int r = i >> 4, cc = i & 15;
            int off = ((cc >> 3) << 15) + halfoff(r, cc & 7);
            size_t g = (size_t)(rowbase + r) * DD + cc * 8;
            cpa16(smb + SM_QHI + off, g_qhi + g);
            cpa16(smb + SM_QLO + off, g_qlo + g);
        }
        load_a(smb, c0 & 1, c0 * COLT);
        load_meta(smb, c0 & 3, c0 * COLT, qid, rnk);
        cpcommit();

        int qrow[8];
        #pragma unroll
        for (int mi = 0; mi < 4; mi++)
            #pragma unroll
            for (int h = 0; h < 2; h++)
                qrow[mi * 2 + h] = qid[rowbase + wm * 64 + mi * 16 + (l >> 2) + h * 8];

        float den[8], num[8], emax[8], emp[8];
        #pragma unroll
        for (int ri = 0; ri < 8; ri++) {
            den[ri] = 0.f; num[ri] = 0.f; emax[ri] = 0.f; emp[ri] = 0.f;
        }

        cpwait0();
        __syncthreads();

        for (int j = c0; j < c1; j++) {
            if (j + 1 < c1) {
                load_a(smb, (j + 1) & 1, (j + 1) * COLT);
                load_meta(smb, (j + 1) & 3, (j + 1) * COLT, qid, rnk);
                cpcommit();
            }
            const uint32_t sma = smb + SM_A(j & 1);
            const int ps = (j - 1) & 3;
            if (j > c0) {
                if (j & 1) tile_step<1>(sm, smb, sma, ps, accB, accA, qrow,
                                        den, num, emax, emp, l, wn, x, subA, subB, rAoff, rBoff);
                else       tile_step<1>(sm, smb, sma, ps, accA, accB, qrow,
                                        den, num, emax, emp, l, wn, x, subA, subB, rAoff, rBoff);
            } else {
                if (j & 1) tile_step<0>(sm, smb, sma, 0, accB, accA, qrow,
                                        den, num, emax, emp, l, wn, x, subA, subB, rAoff, rBoff);
                else       tile_step<0>(sm, smb, sma, 0, accA, accB, qrow,
                                        den, num, emax, emp, l, wn, x, subA, subB, rAoff, rBoff);
            }
            if (j + 1 < c1) cpwait0();
            __syncthreads();
        }
        {   // drain epilogue of last tile
            const int ps = (c1 - 1) & 3;
            if ((c1 - 1) & 1) drain_ep(sm, ps, accB, qrow, den, num, emax, emp, l, wn);
            else              drain_ep(sm, ps, accA, qrow, den, num, emax, emp, l, wn);
        }

        // ---- reduce: lane quads, then 2 wn warps via smem, then atomics ----
        #pragma unroll
        for (int ri = 0; ri < 8; ri++) {
            #pragma unroll
            for (int o = 1; o <= 2; o <<= 1) {
                den[ri]  += __shfl_xor_sync(0xffffffffu, den[ri], o);
                num[ri]  += __shfl_xor_sync(0xffffffffu, num[ri], o);
                emax[ri]  = fmaxf(emax[ri], __shfl_xor_sync(0xffffffffu, emax[ri], o));
                emp[ri]   = fmaxf(emp[ri],  __shfl_xor_sync(0xffffffffu, emp[ri],  o));
            }
        }
        float* sden = (float*)(sm + SM_RED);              // [2][256]
        float* snum = (float*)(sm + SM_RED + 2048);
        float* smx  = (float*)(sm + SM_RED + 4096);
        float* smp  = (float*)(sm + SM_RED + 6144);
        if ((l & 3) == 0) {
            #pragma unroll
            for (int mi = 0; mi < 4; mi++)
                #pragma unroll
                for (int h = 0; h < 2; h++) {
                    int ri = mi * 2 + h;
                    int row = wm * 64 + mi * 16 + (l >> 2) + h * 8;
                    sden[wn * 256 + row] = den[ri];
                    snum[wn * 256 + row] = num[ri];
                    smx [wn * 256 + row] = emax[ri];
                    smp [wn * 256 + row] = emp[ri];
                }
        }
        __syncthreads();
        {
            float d = 0.f, n = 0.f, mx = 0.f, mp = 0.f;
            #pragma unroll
            for (int w = 0; w < 2; w++) {
                d += sden[w * 256 + tid];
                n += snum[w * 256 + tid];
                mx = fmaxf(mx, smx[w * 256 + tid]);
                mp = fmaxf(mp, smp[w * 256 + tid]);
            }
            atomicAdd(&g_den[rowbase + tid], d);
            atomicAdd(&g_num[rowbase + tid], n);
            atomicMax(&g_emax[rowbase + tid], __float_as_int(mx));
            atomicMax(&g_emp[rowbase + tid], __float_as_int(mp));
        }
        __syncthreads();
    }
}

// -------------------- tail: loss + accuracy (one block) --------------------
extern "C" __global__ void mpl_tail(float* out, int B, int osz) {
    const int tid = threadIdx.x;
    float ls = 0.f;
    int cs = 0;
    for (int r = tid; r < B; r += 1024) {
        float d = g_den[r], n = g_num[r];
        float mx = __int_as_float(g_emax[r]);
        float mp = __int_as_float(g_emp[r]);
        ls += -logf(n / d + 1e-8f);
        cs += (mp >= mx) ? 1 : 0;
    }
    __shared__ float sf[1024];
    __shared__ int   si[1024];
    sf[tid] = ls; si[tid] = cs;
    __syncthreads();
    for (int o = 512; o > 0; o >>= 1) {
        if (tid < o) { sf[tid] += sf[tid + o]; si[tid] += si[tid + o]; }
        __syncthreads();
    }
    if (tid == 0) {
        out[0] = sf[0] / (float)B;
        if (osz > 1) out[1] = (float)si[0] / (float)B;
    }
}

extern "C" void kernel_launch(void* const* d_in, const int* in_sizes, int n_in,
                              void* d_out, int out_size) {
    const float* Q   = (const float*)d_in[0];
    const float* A   = (const float*)d_in[1];
    const int*   qid = (const int*)d_in[2];
    const float* rnk = (const float*)d_in[3];
    const int B = in_sizes[2];
    const int n4 = B * DD / 4;

    mpl_prep<<<(n4 + 255) / 256, 256>>>((const float4*)Q, (const float4*)A, n4);

    cudaFuncSetAttribute(mpl_main, cudaFuncAttributeMaxDynamicSharedMemorySize,
                         SMEM_TOTAL);
    mpl_main<<<NSM, NTH, SMEM_TOTAL>>>(qid, rnk, B);

    mpl_tail<<<1, 1024>>>((float*)d_out, B, out_size);
}